// round 15
// baseline (speedup 1.0000x reference)
#include <cuda_runtime.h>
#include <cuda_fp16.h>
#include <math.h>
#include <stdint.h>

#define BSZ   512
#define LEN   100
#define NCAND 64
#define DIM   256
#define KIN   32

typedef unsigned long long u64;

// Scratch (no allocations allowed)
__device__ float  g_proj[BSZ * LEN * DIM];          // 52.4 MB
__device__ float  g_scores[BSZ * KIN * LEN];        // [b][k][l]
__device__ __half g_h1[256 * 256];                  // W splits
__device__ __half g_h2[256 * 256];

// ---- packed fp32x2 helpers --------------------------------------------------
__device__ __forceinline__ u64 ffma2(u64 a, u64 b, u64 c) {
    u64 d;
    asm("fma.rn.f32x2 %0, %1, %2, %3;" : "=l"(d) : "l"(a), "l"(b), "l"(c));
    return d;
}
__device__ __forceinline__ u64 packu(uint32_t a, uint32_t b) {
    u64 r;
    asm("mov.b64 %0, {%1, %2};" : "=l"(r) : "r"(a), "r"(b));
    return r;
}
__device__ __forceinline__ float2 unpack2(u64 v) {
    float2 r;
    asm("mov.b64 {%0, %1}, %2;" : "=f"(r.x), "=f"(r.y) : "l"(v));
    return r;
}

// ---- mma.sync helpers ---------------------------------------------------------
__device__ __forceinline__ uint32_t smem_u32(const void* p) {
    uint32_t a;
    asm("{ .reg .u64 t; cvta.to.shared.u64 t, %1; cvt.u32.u64 %0, t; }" : "=r"(a) : "l"(p));
    return a;
}
__device__ __forceinline__ void ldsm4(uint32_t* r, uint32_t addr) {
    asm volatile("ldmatrix.sync.aligned.m8n8.x4.shared.b16 {%0,%1,%2,%3}, [%4];"
                 : "=r"(r[0]), "=r"(r[1]), "=r"(r[2]), "=r"(r[3]) : "r"(addr) : "memory");
}
__device__ __forceinline__ void ldsm4t(uint32_t* r, uint32_t addr) {
    asm volatile("ldmatrix.sync.aligned.m8n8.x4.trans.shared.b16 {%0,%1,%2,%3}, [%4];"
                 : "=r"(r[0]), "=r"(r[1]), "=r"(r[2]), "=r"(r[3]) : "r"(addr) : "memory");
}
__device__ __forceinline__ void mma16816(float* d, const uint32_t* a, uint32_t b0, uint32_t b1) {
    asm volatile("mma.sync.aligned.m16n8k16.row.col.f32.f16.f16.f32 "
                 "{%0,%1,%2,%3}, {%4,%5,%6,%7}, {%8,%9}, {%0,%1,%2,%3};"
                 : "+f"(d[0]), "+f"(d[1]), "+f"(d[2]), "+f"(d[3])
                 : "r"(a[0]), "r"(a[1]), "r"(a[2]), "r"(a[3]), "r"(b0), "r"(b1));
}
__device__ __forceinline__ void cpasync16(uint32_t smem_addr, const void* gptr) {
    asm volatile("cp.async.ca.shared.global [%0], [%1], 16;"
                 :: "r"(smem_addr), "l"(gptr) : "memory");
}
#define CP_COMMIT() asm volatile("cp.async.commit_group;" ::: "memory")
#define CP_WAIT(n)  asm volatile("cp.async.wait_group %0;" :: "n"(n) : "memory")

#define SWZ(o) ((o) ^ (((o) >> 3) & 0x70))

__device__ __forceinline__ uint32_t h2_u32(__half a, __half b) {
    __half2 t(a, b);
    return *reinterpret_cast<uint32_t*>(&t);
}
__device__ __forceinline__ void split_pack(float x, float y, uint32_t& lo, uint32_t& hi) {
    const __half ax = __float2half_rn(x), ay = __float2half_rn(y);
    const __half bx = __float2half_rn(x - __half2float(ax));
    const __half by = __float2half_rn(y - __half2float(ay));
    lo = h2_u32(ax, ay);
    hi = h2_u32(bx, by);
}

// ---------------------------------------------------------------------------
// W split: once, into g_h1/g_h2
// ---------------------------------------------------------------------------
__global__ void kw_split(const float* __restrict__ W) {
    const int i = blockIdx.x * 256 + threadIdx.x;
    const float a = W[i];
    const __half h1 = __float2half_rn(a);
    g_h1[i] = h1;
    g_h2[i] = __float2half_rn(a - __half2float(h1));
}

// ---------------------------------------------------------------------------
// K1: proj = tanh(hist @ W^T) via mma.sync fp16, 2-level split (3 passes).
// B from pre-split g_h1/g_h2 (pure uint4 copies).
// ---------------------------------------------------------------------------
#define A_OFF  0
#define B_OFF  32768
#define LVL    16384
#define K1_SMEM (65536 + 1024)

__global__ void __launch_bounds__(256, 2) k1_mma(const float* __restrict__ hist) {
    extern __shared__ char smem_raw[];
    const int tid = threadIdx.x;
    const int wid = tid >> 5;
    const int lane = tid & 31;
    const int warp_m = wid >> 2;
    const int warp_n = wid & 3;
    const int m0 = blockIdx.y * 128;
    const int n0 = blockIdx.x * 128;

    const uint32_t sb_raw = smem_u32(smem_raw);
    const uint32_t sb = (sb_raw + 1023u) & ~1023u;
    char* smem = smem_raw + (sb - sb_raw);

    const int g  = lane >> 3;
    const int rw = lane & 7;

    float acc[4][4][4];
#pragma unroll
    for (int mt = 0; mt < 4; mt++)
#pragma unroll
        for (int nt = 0; nt < 4; nt++)
#pragma unroll
            for (int i = 0; i < 4; i++) acc[mt][nt][i] = 0.f;

    for (int kc = 0; kc < 4; kc++) {
#pragma unroll
        for (int t = 0; t < 8; t++) {
            const int idx = tid + t * 256;
            const int r = idx >> 4, c4 = idx & 15;
            const float4 a = __ldg((const float4*)&hist[(size_t)(m0 + r) * 256 + kc * 64 + c4 * 4]);
            uint32_t lx, hx, ly, hy;
            split_pack(a.x, a.y, lx, hx);
            split_pack(a.z, a.w, ly, hy);
            const uint32_t off = SWZ((uint32_t)(r * 128 + c4 * 8));
            *(uint2*)(smem + A_OFF + off)       = make_uint2(lx, ly);
            *(uint2*)(smem + A_OFF + LVL + off) = make_uint2(hx, hy);
        }
        {
            const __half* gw[2] = {g_h1, g_h2};
#pragma unroll
            for (int lv = 0; lv < 2; lv++) {
#pragma unroll
                for (int t = 0; t < 4; t++) {
                    const int idx = tid + t * 256;
                    const int n = idx >> 3, u = idx & 7;
                    const uint4 v = *(const uint4*)&gw[lv][(size_t)(n0 + n) * 256 + kc * 64 + u * 8];
                    *(uint4*)(smem + B_OFF + lv * LVL + SWZ((uint32_t)(n * 128 + u * 16))) = v;
                }
            }
        }
        __syncthreads();

#pragma unroll
        for (int ks = 0; ks < 4; ks++) {
            const int k0 = ks * 16;
            uint32_t aoff[4], boff[2];
#pragma unroll
            for (int mt = 0; mt < 4; mt++) {
                const int row = warp_m * 64 + mt * 16 + ((g & 1) << 3) + rw;
                const int kk  = k0 + ((g >> 1) << 3);
                aoff[mt] = sb + A_OFF + SWZ((uint32_t)(row * 128 + kk * 2));
            }
#pragma unroll
            for (int nt2 = 0; nt2 < 2; nt2++) {
                const int row = warp_n * 32 + nt2 * 16 + ((g >> 1) << 3) + rw;
                const int kk  = k0 + ((g & 1) << 3);
                boff[nt2] = sb + B_OFF + SWZ((uint32_t)(row * 128 + kk * 2));
            }

            uint32_t a0[4][4], a1[4][4], b0[2][4], b1[2][4];
#pragma unroll
            for (int mt = 0; mt < 4; mt++) { ldsm4(a0[mt], aoff[mt]); ldsm4(a1[mt], aoff[mt] + LVL); }
#pragma unroll
            for (int nt2 = 0; nt2 < 2; nt2++) { ldsm4(b0[nt2], boff[nt2]); ldsm4(b1[nt2], boff[nt2] + LVL); }

#pragma unroll
            for (int mt = 0; mt < 4; mt++)
#pragma unroll
                for (int nt = 0; nt < 4; nt++) {
                    const int h = nt >> 1, q = (nt & 1) * 2;
                    mma16816(acc[mt][nt], a0[mt], b0[h][q], b0[h][q + 1]);
                    mma16816(acc[mt][nt], a0[mt], b1[h][q], b1[h][q + 1]);
                    mma16816(acc[mt][nt], a1[mt], b0[h][q], b0[h][q + 1]);
                }
        }
        __syncthreads();
    }

    const int gid = lane >> 2, tig = lane & 3;
#pragma unroll
    for (int mt = 0; mt < 4; mt++) {
#pragma unroll
        for (int nt = 0; nt < 4; nt++) {
            const int row = m0 + warp_m * 64 + mt * 16 + gid;
            const int col = n0 + warp_n * 32 + nt * 8 + tig * 2;
            float2 v0, v1;
            v0.x = tanhf(acc[mt][nt][0]); v0.y = tanhf(acc[mt][nt][1]);
            v1.x = tanhf(acc[mt][nt][2]); v1.y = tanhf(acc[mt][nt][3]);
            *(float2*)&g_proj[(size_t)row * 256 + col]       = v0;
            *(float2*)&g_proj[(size_t)(row + 8) * 256 + col] = v1;
        }
    }
}

// ---------------------------------------------------------------------------
// K2a: scores = g_proj @ codes^T  (unchanged)
// ---------------------------------------------------------------------------
__global__ void __launch_bounds__(128) k2a_kernel(const float* __restrict__ codes) {
    __shared__ __align__(16) char Asm[2][16384];
    __shared__ __align__(16) char Bsm[2][4096];

    const int tid = threadIdx.x;
    const int w = tid >> 5;
    const int lane = tid & 31;
    const int m0 = blockIdx.x * 128;
    const int g = lane >> 3, rw = lane & 7;
    const uint32_t sbA = smem_u32(Asm);
    const uint32_t sbB = smem_u32(Bsm);

    float acc[2][4][4];
#pragma unroll
    for (int mt = 0; mt < 2; mt++)
#pragma unroll
        for (int nt = 0; nt < 4; nt++)
#pragma unroll
            for (int i = 0; i < 4; i++) acc[mt][nt][i] = 0.f;

    for (int kc = 0; kc < 4; kc++) {
#pragma unroll
        for (int t = 0; t < 16; t++) {
            const int idx = tid + t * 128;
            const int r = idx >> 4, c4 = idx & 15;
            const float4 a = __ldg((const float4*)&g_proj[(size_t)(m0 + r) * 256 + kc * 64 + c4 * 4]);
            uint32_t lx, hx, ly, hy;
            split_pack(a.x, a.y, lx, hx);
            split_pack(a.z, a.w, ly, hy);
            const uint32_t off = SWZ((uint32_t)(r * 128 + c4 * 8));
            *(uint2*)(Asm[0] + off) = make_uint2(lx, ly);
            *(uint2*)(Asm[1] + off) = make_uint2(hx, hy);
        }
#pragma unroll
        for (int t = 0; t < 4; t++) {
            const int idx = tid + t * 128;
            const int r = idx >> 4, c4 = idx & 15;
            const float4 a = __ldg((const float4*)&codes[(size_t)r * 256 + kc * 64 + c4 * 4]);
            uint32_t lx, hx, ly, hy;
            split_pack(a.x, a.y, lx, hx);
            split_pack(a.z, a.w, ly, hy);
            const uint32_t off = SWZ((uint32_t)(r * 128 + c4 * 8));
            *(uint2*)(Bsm[0] + off) = make_uint2(lx, ly);
            *(uint2*)(Bsm[1] + off) = make_uint2(hx, hy);
        }
        __syncthreads();

#pragma unroll
        for (int ks = 0; ks < 4; ks++) {
            const int k0 = ks * 16;
            uint32_t aoff[2], boff[2];
#pragma unroll
            for (int mt = 0; mt < 2; mt++) {
                const int row = w * 32 + mt * 16 + ((g & 1) << 3) + rw;
                aoff[mt] = sbA + SWZ((uint32_t)(row * 128 + (k0 + ((g >> 1) << 3)) * 2));
            }
#pragma unroll
            for (int nt2 = 0; nt2 < 2; nt2++) {
                const int row = nt2 * 16 + ((g >> 1) << 3) + rw;
                boff[nt2] = sbB + SWZ((uint32_t)(row * 128 + (k0 + ((g & 1) << 3)) * 2));
            }
            uint32_t a0[2][4], a1[2][4], b0[2][4], b1[2][4];
#pragma unroll
            for (int mt = 0; mt < 2; mt++) { ldsm4(a0[mt], aoff[mt]); ldsm4(a1[mt], aoff[mt] + 16384); }
#pragma unroll
            for (int nt2 = 0; nt2 < 2; nt2++) { ldsm4(b0[nt2], boff[nt2]); ldsm4(b1[nt2], boff[nt2] + 4096); }
#pragma unroll
            for (int mt = 0; mt < 2; mt++)
#pragma unroll
                for (int nt = 0; nt < 4; nt++) {
                    const int h = nt >> 1, q = (nt & 1) * 2;
                    mma16816(acc[mt][nt], a0[mt], b0[h][q], b0[h][q + 1]);
                    mma16816(acc[mt][nt], a0[mt], b1[h][q], b1[h][q + 1]);
                    mma16816(acc[mt][nt], a1[mt], b0[h][q], b0[h][q + 1]);
                    mma16816(acc[mt][nt], a1[mt], b1[h][q], b1[h][q + 1]);
                }
        }
        __syncthreads();
    }

    const int gid = lane >> 2, tig = lane & 3;
#pragma unroll
    for (int mt = 0; mt < 2; mt++) {
#pragma unroll
        for (int nt = 0; nt < 4; nt++) {
            const int col = nt * 8 + tig * 2;
#pragma unroll
            for (int half = 0; half < 2; half++) {
                const int M = m0 + w * 32 + mt * 16 + gid + half * 8;
                const int b = M / 100, l = M - b * 100;
                float* dst = g_scores + (size_t)b * 3200 + l;
                dst[(size_t)col * 100]       = acc[mt][nt][half * 2];
                dst[(size_t)(col + 1) * 100] = acc[mt][nt][half * 2 + 1];
            }
        }
    }
}

// ---------------------------------------------------------------------------
// K24: per-batch fused  softmax -> interests(mma) -> w(fp32) -> rank -> user(mma).
// cp.async double-buffered candidate loads (R14 version, measured win).
// ---------------------------------------------------------------------------
#define O_ASM   0
#define O_BSM   16384
#define O_IF32  0
#define O_CAND0 0
#define O_CAND1 8192
#define O_PART  16384
#define O_WMT   24576
#define O_WMS   0
#define O_ISM   49152
#define K24_SMEM (81920 + 1024)

__global__ void __launch_bounds__(256, 2) k24(const float* __restrict__ hist,
                                              const int* __restrict__ numInt,
                                              const float* __restrict__ cand,
                                              const int* __restrict__ catCnt,
                                              float* __restrict__ out) {
    extern __shared__ char raw[];
    const int b = blockIdx.x;
    const int tid = threadIdx.x;
    const int w = tid >> 5;
    const int lane = tid & 31;
    const int g = lane >> 3, rw = lane & 7;
    const int gid = lane >> 2, tig = lane & 3;

    const uint32_t sbr = smem_u32(raw);
    const uint32_t sb = (sbr + 1023u) & ~1023u;
    char* s = raw + (sb - sbr);

    char* Asm = s + O_ASM;
    char* Bsm = s + O_BSM;
    char* ism = s + O_ISM;
    float* if32 = (float*)(s + O_IF32);
    const uint32_t uA = sb + O_ASM, uB = sb + O_BSM, uI = sb + O_ISM;

    // ================= Phase 1: softmax =================
    float* sc = (float*)Bsm;
    {
        const float* src = g_scores + (size_t)b * 3200;
        for (int idx = tid; idx < 3200; idx += 256) sc[idx] = src[idx];
    }
    __syncthreads();
    {
        const int ni = numInt[b];
        for (int k = w; k < 32; k += 8) {
            if (k >= ni) {
                for (int l = lane; l < LEN; l += 32) sc[k * 100 + l] = 0.01f;
            } else {
                float m = -3.4e38f;
                for (int l = lane; l < LEN; l += 32) m = fmaxf(m, sc[k * 100 + l]);
#pragma unroll
                for (int off = 16; off; off >>= 1)
                    m = fmaxf(m, __shfl_xor_sync(0xffffffffu, m, off));
                float ssum = 0.f;
                for (int l = lane; l < LEN; l += 32) {
                    float e = expf(sc[k * 100 + l] - m);
                    sc[k * 100 + l] = e;
                    ssum += e;
                }
#pragma unroll
                for (int off = 16; off; off >>= 1) ssum += __shfl_xor_sync(0xffffffffu, ssum, off);
                for (int l = lane; l < LEN; l += 32) sc[k * 100 + l] = sc[k * 100 + l] / ssum;
            }
        }
    }
    __syncthreads();

    // ================= Phase 2: attn splits -> Asm =================
    for (int idx = tid; idx < 2048; idx += 256) {
        const int k = idx >> 6;
        const int l2 = (idx & 63) * 2;
        const float v0 = (l2 < 100) ? sc[k * 100 + l2] : 0.f;
        const float v1 = (l2 + 1 < 100) ? sc[k * 100 + l2 + 1] : 0.f;
        uint32_t lo, hi;
        split_pack(v0, v1, lo, hi);
        const int h = l2 >> 6, ll = l2 & 63;
        const uint32_t off = SWZ((uint32_t)((h * 32 + k) * 128 + ll * 2));
        *(uint32_t*)(Asm + off)        = lo;
        *(uint32_t*)(Asm + 8192 + off) = hi;
    }
    __syncthreads();

    // ================= Phase 3: interests mma =================
    const int pnl = w >> 1;
    const int sub = w & 1;
    float acc[2][2][2][4];
#pragma unroll
    for (int mt = 0; mt < 2; mt++)
#pragma unroll
        for (int ntt = 0; ntt < 2; ntt++)
#pragma unroll
            for (int n8 = 0; n8 < 2; n8++)
#pragma unroll
                for (int i = 0; i < 4; i++) acc[mt][ntt][n8][i] = 0.f;

    const float* Hb = hist + (size_t)b * LEN * DIM;
    for (int ch = 0; ch < 4; ch++) {
        const int l0 = ch * 32;
#pragma unroll
        for (int t = 0; t < 8; t++) {
            const int idx = tid + t * 256;
            const int lr = idx >> 6, c4 = idx & 63;
            const int l = l0 + lr;
            float4 a = make_float4(0.f, 0.f, 0.f, 0.f);
            if (l < LEN) a = __ldg((const float4*)&Hb[(size_t)l * 256 + c4 * 4]);
            uint32_t lx, hx, ly, hy;
            split_pack(a.x, a.y, lx, hx);
            split_pack(a.z, a.w, ly, hy);
            const int d = c4 * 4;
            const int p = d >> 6, dcol = d & 63;
            const uint32_t off = p * 4096 + SWZ((uint32_t)(lr * 128 + dcol * 2));
            *(uint2*)(Bsm + off)         = make_uint2(lx, ly);
            *(uint2*)(Bsm + 16384 + off) = make_uint2(hx, hy);
        }
        __syncthreads();

#pragma unroll
        for (int ks2 = 0; ks2 < 2; ks2++) {
            const int kk = l0 + ks2 * 16;
            const int half = kk >> 6, lloc = kk & 63;

            uint32_t a0[2][4], a1[2][4];
#pragma unroll
            for (int mt = 0; mt < 2; mt++) {
                const int row = mt * 16 + ((g & 1) << 3) + rw;
                const uint32_t ao = SWZ((uint32_t)((half * 32 + row) * 128 + (lloc + ((g >> 1) << 3)) * 2));
                ldsm4(a0[mt], uA + ao);
                ldsm4(a1[mt], uA + 8192 + ao);
            }

            const int trow = ks2 * 16 + (lane & 7) + ((lane >> 3) & 1) * 8;
            const int tcolb = ((lane >> 4) & 1) * 8;
#pragma unroll
            for (int ntt = 0; ntt < 2; ntt++) {
                const int ntg = sub * 2 + ntt;
                const uint32_t bo = pnl * 4096 + SWZ((uint32_t)(trow * 128 + (ntg * 16 + tcolb) * 2));
                uint32_t bl0[4], bl1[4];
                ldsm4t(bl0, uB + bo);
                ldsm4t(bl1, uB + 16384 + bo);
#pragma unroll
                for (int mt = 0; mt < 2; mt++) {
                    float* c0 = acc[mt][ntt][0];
                    float* c1 = acc[mt][ntt][1];
                    mma16816(c0, a0[mt], bl0[0], bl0[1]);
                    mma16816(c0, a0[mt], bl1[0], bl1[1]);
                    mma16816(c0, a1[mt], bl0[0], bl0[1]);
                    mma16816(c0, a1[mt], bl1[0], bl1[1]);
                    mma16816(c1, a0[mt], bl0[2], bl0[3]);
                    mma16816(c1, a0[mt], bl1[2], bl1[3]);
                    mma16816(c1, a1[mt], bl0[2], bl0[3]);
                    mma16816(c1, a1[mt], bl1[2], bl1[3]);
                }
            }
        }
        __syncthreads();
    }

    // ================= Phase 4: interests -> if32 + ism =================
#pragma unroll
    for (int mt = 0; mt < 2; mt++) {
#pragma unroll
        for (int ntt = 0; ntt < 2; ntt++) {
            const int ntg = sub * 2 + ntt;
#pragma unroll
            for (int n8 = 0; n8 < 2; n8++) {
                const int d = pnl * 64 + ntg * 16 + n8 * 8 + tig * 2;
#pragma unroll
                for (int hh = 0; hh < 2; hh++) {
                    const int kk = mt * 16 + gid + hh * 8;
                    const float vx = acc[mt][ntt][n8][hh * 2], vy = acc[mt][ntt][n8][hh * 2 + 1];
                    *(float2*)&if32[kk * 256 + d] = make_float2(vx, vy);
                    uint32_t lo, hi;
                    split_pack(vx, vy, lo, hi);
                    const int dloc = d & 63;
                    const uint32_t off = pnl * 4096 + SWZ((uint32_t)(kk * 128 + dloc * 2));
                    *(uint32_t*)(ism + off)         = lo;
                    *(uint32_t*)(ism + 16384 + off) = hi;
                }
            }
        }
    }
    __syncthreads();

    // ================= Phase 5: w-GEMM + rank, cp.async pipeline =================
    float* partial = (float*)(s + O_PART);
    float* wmaskT  = (float*)(s + O_WMT);
    const uint32_t uC0 = sb + O_CAND0, uC1 = sb + O_CAND1;

    u64 ireg2[16];
    {
        const u64* ibase = (const u64*)(if32 + lane * 256 + w * 32);
#pragma unroll
        for (int j = 0; j < 16; j++) ireg2[j] = ibase[j];
    }
    __syncthreads();

    const int cc = catCnt[b];
    int dynK = (int)ceilf(log2f(8.0f * (float)cc));
    dynK = dynK < 1 ? 1 : (dynK > 32 ? 32 : dynK);

    const float* Cb = cand + (size_t)b * NCAND * DIM;

    cpasync16(uC0 + tid * 16, Cb + tid * 4);
    cpasync16(uC0 + (tid + 256) * 16, Cb + (size_t)(tid + 256) * 4);
    CP_COMMIT();

    for (int n0 = 0; n0 < 64; n0 += 8) {
        const int buf = (n0 >> 3) & 1;
        if (n0 + 8 < 64) {
            const uint32_t uNxt = buf ? uC0 : uC1;
            const float* src = Cb + (size_t)(n0 + 8) * DIM;
            cpasync16(uNxt + tid * 16, src + tid * 4);
            cpasync16(uNxt + (tid + 256) * 16, src + (size_t)(tid + 256) * 4);
            CP_COMMIT();
            CP_WAIT(1);
        } else {
            CP_WAIT(0);
        }
        __syncthreads();

        const uint4* rbase4 = (const uint4*)(s + (buf ? O_CAND1 : O_CAND0));
        u64 p[8];
#pragma unroll
        for (int r = 0; r < 8; r++) p[r] = 0ull;
#pragma unroll
        for (int j4 = 0; j4 < 8; j4++) {
            const u64 iv0 = ireg2[j4 * 2], iv1 = ireg2[j4 * 2 + 1];
            const int coff = w * 8 + j4;
#pragma unroll
            for (int r = 0; r < 8; r++) {
                const uint4 v = rbase4[r * 64 + coff];
                p[r] = ffma2(iv0, packu(v.x, v.y), p[r]);
                p[r] = ffma2(iv1, packu(v.z, v.w), p[r]);
            }
        }
#pragma unroll
        for (int r = 0; r < 8; r++) {
            float2 t = unpack2(p[r]);
            partial[w * 256 + r * 32 + lane] = t.x + t.y;
        }
        __syncthreads();

        {
            const int k = lane, r = w;
            float ssum = 0.f;
#pragma unroll
            for (int ww = 0; ww < 8; ww++) ssum += partial[ww * 256 + r * 32 + k];
            wmaskT[(n0 + r) * 32 + k] = ssum;
        }
        __syncwarp();

        {
            const float wi = wmaskT[(n0 + w) * 32 + lane];
            int rank = 0;
#pragma unroll
            for (int j = 0; j < 32; j++) {
                const float wj = __shfl_sync(0xffffffffu, wi, j);
                rank += (wj > wi) || (wj == wi && j < lane);
            }
            wmaskT[(n0 + w) * 32 + lane] = (rank < dynK) ? wi : 0.f;
        }
        __syncthreads();
    }

    // ================= Phase 6: wmask fp16 splits =================
    char* wmsm = s + O_WMS;
    const uint32_t uW = sb + O_WMS;
    for (int idx = tid; idx < 2048; idx += 256) {
        const int r = idx >> 5, c = idx & 31;
        const float v = wmaskT[r * 32 + c];
        const __half m1 = __float2half_rn(v);
        const __half m2 = __float2half_rn(v - __half2float(m1));
        const uint32_t off = SWZ((uint32_t)(r * 128 + c * 2));
        *(__half*)(wmsm + off)        = m1;
        *(__half*)(wmsm + 8192 + off) = m2;
    }
    __syncthreads();

    // ================= Phase 7: user mma (3-pass) =================
    const int mt = w & 3;
    const int phh = w >> 2;

    float* Ob = out + (size_t)b * NCAND * DIM;
#pragma unroll
    for (int pp = 0; pp < 2; pp++) {
        const int pn = phh * 2 + pp;

        float ua[4][2][4];
#pragma unroll
        for (int ntt = 0; ntt < 4; ntt++)
#pragma unroll
            for (int n8 = 0; n8 < 2; n8++)
#pragma unroll
                for (int i = 0; i < 4; i++) ua[ntt][n8][i] = 0.f;

#pragma unroll
        for (int ks = 0; ks < 2; ks++) {
            const int arow = mt * 16 + ((g & 1) << 3) + rw;
            const int acol = ks * 16 + ((g >> 1) << 3);
            const uint32_t ao = SWZ((uint32_t)(arow * 128 + acol * 2));
            uint32_t am1[4], am2[4];
            ldsm4(am1, uW + ao);
            ldsm4(am2, uW + 8192 + ao);

            const int trow = ks * 16 + (lane & 7) + ((lane >> 3) & 1) * 8;
            const int tcolb = ((lane >> 4) & 1) * 8;
#pragma unroll
            for (int ntt = 0; ntt < 4; ntt++) {
                const uint32_t bo = pn * 4096 + SWZ((uint32_t)(trow * 128 + (ntt * 16 + tcolb) * 2));
                uint32_t bi1[4], bi2[4];
                ldsm4t(bi1, uI + bo);
                ldsm4t(bi2, uI + 16384 + bo);
#pragma unroll
                for (int n8 = 0; n8 < 2; n8++) {
                    float* c = ua[ntt][n8];
                    mma16816(c, am1, bi1[n8 * 2], bi1[n8 * 2 + 1]);
                    mma16816(c, am1, bi2[n8 * 2], bi2[n8 * 2 + 1]);
                    mma16816(c, am2, bi1[n8 * 2], bi1[n8 * 2 + 1]);
                }
            }
        }

#pragma unroll
        for (int ntt = 0; ntt < 4; ntt++) {
#pragma unroll
            for (int n8 = 0; n8 < 2; n8++) {
                const int d = pn * 64 + ntt * 16 + n8 * 8 + tig * 2;
                const int r0 = mt * 16 + gid;
                *(float2*)&Ob[(size_t)r0 * 256 + d]       = make_float2(ua[ntt][n8][0], ua[ntt][n8][1]);
                *(float2*)&Ob[(size_t)(r0 + 8) * 256 + d] = make_float2(ua[ntt][n8][2], ua[ntt][n8][3]);
            }
        }
    }
}

// ---------------------------------------------------------------------------
extern "C" void kernel_launch(void* const* d_in, const int* in_sizes, int n_in,
                              void* d_out, int out_size) {
    (void)in_sizes; (void)n_in; (void)out_size;
    const float* hist  = (const float*)d_in[0];
    const float* cand  = (const float*)d_in[2];
    const int*   numI  = (const int*)d_in[3];
    const int*   catC  = (const int*)d_in[4];
    const float* W     = (const float*)d_in[5];
    const float* codes = (const float*)d_in[6];
    float* out = (float*)d_out;

    static bool attr_set = false;
    if (!attr_set) {
        cudaFuncSetAttribute(k1_mma, cudaFuncAttributeMaxDynamicSharedMemorySize, K1_SMEM);
        cudaFuncSetAttribute(k24, cudaFuncAttributeMaxDynamicSharedMemorySize, K24_SMEM);
        attr_set = true;
    }

    kw_split<<<256, 256>>>(W);
    k1_mma<<<dim3(2, 400), 256, K1_SMEM>>>(hist);
    k2a_kernel<<<400, 128>>>(codes);
    k24<<<BSZ, 256, K24_SMEM>>>(hist, numI, cand, catC, out);
}

// round 16
// speedup vs baseline: 1.0300x; 1.0300x over previous
#include <cuda_runtime.h>
#include <cuda_fp16.h>
#include <math.h>
#include <stdint.h>

#define BSZ   512
#define LEN   100
#define NCAND 64
#define DIM   256
#define KIN   32

typedef unsigned long long u64;

// Scratch (no allocations allowed)
__device__ float  g_proj[BSZ * LEN * DIM];          // 52.4 MB
__device__ float  g_scores[BSZ * KIN * LEN];        // [b][k][l]
__device__ __half g_h1[256 * 256];                  // W splits
__device__ __half g_h2[256 * 256];

// ---- packed fp32x2 helpers --------------------------------------------------
__device__ __forceinline__ u64 ffma2(u64 a, u64 b, u64 c) {
    u64 d;
    asm("fma.rn.f32x2 %0, %1, %2, %3;" : "=l"(d) : "l"(a), "l"(b), "l"(c));
    return d;
}
__device__ __forceinline__ u64 packu(uint32_t a, uint32_t b) {
    u64 r;
    asm("mov.b64 %0, {%1, %2};" : "=l"(r) : "r"(a), "r"(b));
    return r;
}
__device__ __forceinline__ float2 unpack2(u64 v) {
    float2 r;
    asm("mov.b64 {%0, %1}, %2;" : "=f"(r.x), "=f"(r.y) : "l"(v));
    return r;
}

// ---- mma.sync helpers ---------------------------------------------------------
__device__ __forceinline__ uint32_t smem_u32(const void* p) {
    uint32_t a;
    asm("{ .reg .u64 t; cvta.to.shared.u64 t, %1; cvt.u32.u64 %0, t; }" : "=r"(a) : "l"(p));
    return a;
}
__device__ __forceinline__ void ldsm4(uint32_t* r, uint32_t addr) {
    asm volatile("ldmatrix.sync.aligned.m8n8.x4.shared.b16 {%0,%1,%2,%3}, [%4];"
                 : "=r"(r[0]), "=r"(r[1]), "=r"(r[2]), "=r"(r[3]) : "r"(addr) : "memory");
}
__device__ __forceinline__ void ldsm4t(uint32_t* r, uint32_t addr) {
    asm volatile("ldmatrix.sync.aligned.m8n8.x4.trans.shared.b16 {%0,%1,%2,%3}, [%4];"
                 : "=r"(r[0]), "=r"(r[1]), "=r"(r[2]), "=r"(r[3]) : "r"(addr) : "memory");
}
__device__ __forceinline__ void mma16816(float* d, const uint32_t* a, uint32_t b0, uint32_t b1) {
    asm volatile("mma.sync.aligned.m16n8k16.row.col.f32.f16.f16.f32 "
                 "{%0,%1,%2,%3}, {%4,%5,%6,%7}, {%8,%9}, {%0,%1,%2,%3};"
                 : "+f"(d[0]), "+f"(d[1]), "+f"(d[2]), "+f"(d[3])
                 : "r"(a[0]), "r"(a[1]), "r"(a[2]), "r"(a[3]), "r"(b0), "r"(b1));
}
__device__ __forceinline__ void cpasync16(uint32_t smem_addr, const void* gptr) {
    asm volatile("cp.async.ca.shared.global [%0], [%1], 16;"
                 :: "r"(smem_addr), "l"(gptr) : "memory");
}
#define CP_COMMIT() asm volatile("cp.async.commit_group;" ::: "memory")
#define CP_WAIT(n)  asm volatile("cp.async.wait_group %0;" :: "n"(n) : "memory")

#define SWZ(o) ((o) ^ (((o) >> 3) & 0x70))

__device__ __forceinline__ uint32_t h2_u32(__half a, __half b) {
    __half2 t(a, b);
    return *reinterpret_cast<uint32_t*>(&t);
}
__device__ __forceinline__ void split_pack(float x, float y, uint32_t& lo, uint32_t& hi) {
    const __half ax = __float2half_rn(x), ay = __float2half_rn(y);
    const __half bx = __float2half_rn(x - __half2float(ax));
    const __half by = __float2half_rn(y - __half2float(ay));
    lo = h2_u32(ax, ay);
    hi = h2_u32(bx, by);
}

// ---------------------------------------------------------------------------
// W split: once, into g_h1/g_h2
// ---------------------------------------------------------------------------
__global__ void kw_split(const float* __restrict__ W) {
    const int i = blockIdx.x * 256 + threadIdx.x;
    const float a = W[i];
    const __half h1 = __float2half_rn(a);
    g_h1[i] = h1;
    g_h2[i] = __float2half_rn(a - __half2float(h1));
}

// ---------------------------------------------------------------------------
// K1: proj = tanh(hist @ W^T) via mma.sync fp16, 2-level split (3 passes).
// ---------------------------------------------------------------------------
#define A_OFF  0
#define B_OFF  32768
#define LVL    16384
#define K1_SMEM (65536 + 1024)

__global__ void __launch_bounds__(256, 2) k1_mma(const float* __restrict__ hist) {
    extern __shared__ char smem_raw[];
    const int tid = threadIdx.x;
    const int wid = tid >> 5;
    const int lane = tid & 31;
    const int warp_m = wid >> 2;
    const int warp_n = wid & 3;
    const int m0 = blockIdx.y * 128;
    const int n0 = blockIdx.x * 128;

    const uint32_t sb_raw = smem_u32(smem_raw);
    const uint32_t sb = (sb_raw + 1023u) & ~1023u;
    char* smem = smem_raw + (sb - sb_raw);

    const int g  = lane >> 3;
    const int rw = lane & 7;

    float acc[4][4][4];
#pragma unroll
    for (int mt = 0; mt < 4; mt++)
#pragma unroll
        for (int nt = 0; nt < 4; nt++)
#pragma unroll
            for (int i = 0; i < 4; i++) acc[mt][nt][i] = 0.f;

    for (int kc = 0; kc < 4; kc++) {
#pragma unroll
        for (int t = 0; t < 8; t++) {
            const int idx = tid + t * 256;
            const int r = idx >> 4, c4 = idx & 15;
            const float4 a = __ldg((const float4*)&hist[(size_t)(m0 + r) * 256 + kc * 64 + c4 * 4]);
            uint32_t lx, hx, ly, hy;
            split_pack(a.x, a.y, lx, hx);
            split_pack(a.z, a.w, ly, hy);
            const uint32_t off = SWZ((uint32_t)(r * 128 + c4 * 8));
            *(uint2*)(smem + A_OFF + off)       = make_uint2(lx, ly);
            *(uint2*)(smem + A_OFF + LVL + off) = make_uint2(hx, hy);
        }
        {
            const __half* gw[2] = {g_h1, g_h2};
#pragma unroll
            for (int lv = 0; lv < 2; lv++) {
#pragma unroll
                for (int t = 0; t < 4; t++) {
                    const int idx = tid + t * 256;
                    const int n = idx >> 3, u = idx & 7;
                    const uint4 v = *(const uint4*)&gw[lv][(size_t)(n0 + n) * 256 + kc * 64 + u * 8];
                    *(uint4*)(smem + B_OFF + lv * LVL + SWZ((uint32_t)(n * 128 + u * 16))) = v;
                }
            }
        }
        __syncthreads();

#pragma unroll
        for (int ks = 0; ks < 4; ks++) {
            const int k0 = ks * 16;
            uint32_t aoff[4], boff[2];
#pragma unroll
            for (int mt = 0; mt < 4; mt++) {
                const int row = warp_m * 64 + mt * 16 + ((g & 1) << 3) + rw;
                const int kk  = k0 + ((g >> 1) << 3);
                aoff[mt] = sb + A_OFF + SWZ((uint32_t)(row * 128 + kk * 2));
            }
#pragma unroll
            for (int nt2 = 0; nt2 < 2; nt2++) {
                const int row = warp_n * 32 + nt2 * 16 + ((g >> 1) << 3) + rw;
                const int kk  = k0 + ((g & 1) << 3);
                boff[nt2] = sb + B_OFF + SWZ((uint32_t)(row * 128 + kk * 2));
            }

            uint32_t a0[4][4], a1[4][4], b0[2][4], b1[2][4];
#pragma unroll
            for (int mt = 0; mt < 4; mt++) { ldsm4(a0[mt], aoff[mt]); ldsm4(a1[mt], aoff[mt] + LVL); }
#pragma unroll
            for (int nt2 = 0; nt2 < 2; nt2++) { ldsm4(b0[nt2], boff[nt2]); ldsm4(b1[nt2], boff[nt2] + LVL); }

#pragma unroll
            for (int mt = 0; mt < 4; mt++)
#pragma unroll
                for (int nt = 0; nt < 4; nt++) {
                    const int h = nt >> 1, q = (nt & 1) * 2;
                    mma16816(acc[mt][nt], a0[mt], b0[h][q], b0[h][q + 1]);
                    mma16816(acc[mt][nt], a0[mt], b1[h][q], b1[h][q + 1]);
                    mma16816(acc[mt][nt], a1[mt], b0[h][q], b0[h][q + 1]);
                }
        }
        __syncthreads();
    }

    const int gid = lane >> 2, tig = lane & 3;
#pragma unroll
    for (int mt = 0; mt < 4; mt++) {
#pragma unroll
        for (int nt = 0; nt < 4; nt++) {
            const int row = m0 + warp_m * 64 + mt * 16 + gid;
            const int col = n0 + warp_n * 32 + nt * 8 + tig * 2;
            float2 v0, v1;
            v0.x = tanhf(acc[mt][nt][0]); v0.y = tanhf(acc[mt][nt][1]);
            v1.x = tanhf(acc[mt][nt][2]); v1.y = tanhf(acc[mt][nt][3]);
            *(float2*)&g_proj[(size_t)row * 256 + col]       = v0;
            *(float2*)&g_proj[(size_t)(row + 8) * 256 + col] = v1;
        }
    }
}

// ---------------------------------------------------------------------------
// K2a: scores = g_proj @ codes^T  (unchanged)
// ---------------------------------------------------------------------------
__global__ void __launch_bounds__(128) k2a_kernel(const float* __restrict__ codes) {
    __shared__ __align__(16) char Asm[2][16384];
    __shared__ __align__(16) char Bsm[2][4096];

    const int tid = threadIdx.x;
    const int w = tid >> 5;
    const int lane = tid & 31;
    const int m0 = blockIdx.x * 128;
    const int g = lane >> 3, rw = lane & 7;
    const uint32_t sbA = smem_u32(Asm);
    const uint32_t sbB = smem_u32(Bsm);

    float acc[2][4][4];
#pragma unroll
    for (int mt = 0; mt < 2; mt++)
#pragma unroll
        for (int nt = 0; nt < 4; nt++)
#pragma unroll
            for (int i = 0; i < 4; i++) acc[mt][nt][i] = 0.f;

    for (int kc = 0; kc < 4; kc++) {
#pragma unroll
        for (int t = 0; t < 16; t++) {
            const int idx = tid + t * 128;
            const int r = idx >> 4, c4 = idx & 15;
            const float4 a = __ldg((const float4*)&g_proj[(size_t)(m0 + r) * 256 + kc * 64 + c4 * 4]);
            uint32_t lx, hx, ly, hy;
            split_pack(a.x, a.y, lx, hx);
            split_pack(a.z, a.w, ly, hy);
            const uint32_t off = SWZ((uint32_t)(r * 128 + c4 * 8));
            *(uint2*)(Asm[0] + off) = make_uint2(lx, ly);
            *(uint2*)(Asm[1] + off) = make_uint2(hx, hy);
        }
#pragma unroll
        for (int t = 0; t < 4; t++) {
            const int idx = tid + t * 128;
            const int r = idx >> 4, c4 = idx & 15;
            const float4 a = __ldg((const float4*)&codes[(size_t)r * 256 + kc * 64 + c4 * 4]);
            uint32_t lx, hx, ly, hy;
            split_pack(a.x, a.y, lx, hx);
            split_pack(a.z, a.w, ly, hy);
            const uint32_t off = SWZ((uint32_t)(r * 128 + c4 * 8));
            *(uint2*)(Bsm[0] + off) = make_uint2(lx, ly);
            *(uint2*)(Bsm[1] + off) = make_uint2(hx, hy);
        }
        __syncthreads();

#pragma unroll
        for (int ks = 0; ks < 4; ks++) {
            const int k0 = ks * 16;
            uint32_t aoff[2], boff[2];
#pragma unroll
            for (int mt = 0; mt < 2; mt++) {
                const int row = w * 32 + mt * 16 + ((g & 1) << 3) + rw;
                aoff[mt] = sbA + SWZ((uint32_t)(row * 128 + (k0 + ((g >> 1) << 3)) * 2));
            }
#pragma unroll
            for (int nt2 = 0; nt2 < 2; nt2++) {
                const int row = nt2 * 16 + ((g >> 1) << 3) + rw;
                boff[nt2] = sbB + SWZ((uint32_t)(row * 128 + (k0 + ((g & 1) << 3)) * 2));
            }
            uint32_t a0[2][4], a1[2][4], b0[2][4], b1[2][4];
#pragma unroll
            for (int mt = 0; mt < 2; mt++) { ldsm4(a0[mt], aoff[mt]); ldsm4(a1[mt], aoff[mt] + 16384); }
#pragma unroll
            for (int nt2 = 0; nt2 < 2; nt2++) { ldsm4(b0[nt2], boff[nt2]); ldsm4(b1[nt2], boff[nt2] + 4096); }
#pragma unroll
            for (int mt = 0; mt < 2; mt++)
#pragma unroll
                for (int nt = 0; nt < 4; nt++) {
                    const int h = nt >> 1, q = (nt & 1) * 2;
                    mma16816(acc[mt][nt], a0[mt], b0[h][q], b0[h][q + 1]);
                    mma16816(acc[mt][nt], a0[mt], b1[h][q], b1[h][q + 1]);
                    mma16816(acc[mt][nt], a1[mt], b0[h][q], b0[h][q + 1]);
                    mma16816(acc[mt][nt], a1[mt], b1[h][q], b1[h][q + 1]);
                }
        }
        __syncthreads();
    }

    const int gid = lane >> 2, tig = lane & 3;
#pragma unroll
    for (int mt = 0; mt < 2; mt++) {
#pragma unroll
        for (int nt = 0; nt < 4; nt++) {
            const int col = nt * 8 + tig * 2;
#pragma unroll
            for (int half = 0; half < 2; half++) {
                const int M = m0 + w * 32 + mt * 16 + gid + half * 8;
                const int b = M / 100, l = M - b * 100;
                float* dst = g_scores + (size_t)b * 3200 + l;
                dst[(size_t)col * 100]       = acc[mt][nt][half * 2];
                dst[(size_t)(col + 1) * 100] = acc[mt][nt][half * 2 + 1];
            }
        }
    }
}

// ---------------------------------------------------------------------------
// K24: per-batch fused pipeline, cp.async prefetch for EVERY phase-entry load.
// SMEM (dyn, 1024-aligned base):
//   ph1-3: Asm [0,16K) | Bsm [16K,48K)       (sc overlays Bsm)
//   ph3:   hist fp32 staging = ism region [48K,80K) (single-buffered)
//   ph4:   if32 [0,32K); ism splits [48K,80K)
//   ph5:   partial [0,8K) wmaskT [8K,16K); cand0/cand1 dedicated [80K,96K)
//   ph6-7: wmsm [16K,32K), ism live
// ---------------------------------------------------------------------------
#define O_ASM   0
#define O_BSM   16384
#define O_IF32  0
#define O_PART  0
#define O_WMT   8192
#define O_WMS   16384
#define O_ISM   49152
#define O_CAND0 81920
#define O_CAND1 90112
#define K24_SMEM (98304 + 1024)

__global__ void __launch_bounds__(256, 2) k24(const float* __restrict__ hist,
                                              const int* __restrict__ numInt,
                                              const float* __restrict__ cand,
                                              const int* __restrict__ catCnt,
                                              float* __restrict__ out) {
    extern __shared__ char raw[];
    const int b = blockIdx.x;
    const int tid = threadIdx.x;
    const int w = tid >> 5;
    const int lane = tid & 31;
    const int g = lane >> 3, rw = lane & 7;
    const int gid = lane >> 2, tig = lane & 3;

    const uint32_t sbr = smem_u32(raw);
    const uint32_t sb = (sbr + 1023u) & ~1023u;
    char* s = raw + (sb - sbr);

    char* Asm = s + O_ASM;
    char* Bsm = s + O_BSM;
    char* ism = s + O_ISM;
    float* if32 = (float*)(s + O_IF32);
    float* stage = (float*)(s + O_ISM);      // hist fp32 staging (phase 3)
    const uint32_t uA = sb + O_ASM, uB = sb + O_BSM, uI = sb + O_ISM;
    const uint32_t uS = sb + O_ISM;
    const uint32_t uC0 = sb + O_CAND0, uC1 = sb + O_CAND1;

    const float* Hb = hist + (size_t)b * LEN * DIM;
    const float* Cb = cand + (size_t)b * NCAND * DIM;

    // ===== Kernel-start prologue: prefetch scores, cand rows 0-7, hist chunk 0
    {
        const float* src = g_scores + (size_t)b * 3200;   // 800 uint4
#pragma unroll
        for (int t = 0; t < 4; t++) {
            const int idx = tid + t * 256;
            if (idx < 800) cpasync16(uB + idx * 16, src + idx * 4);
        }
        CP_COMMIT();                                      // group: scores
        cpasync16(uC0 + tid * 16, Cb + tid * 4);
        cpasync16(uC0 + (tid + 256) * 16, Cb + (size_t)(tid + 256) * 4);
        CP_COMMIT();                                      // group: cand rows 0-7
#pragma unroll
        for (int t = 0; t < 8; t++) {
            const int idx = tid + t * 256;                // 2048 uint4 (rows 0-31 all valid)
            cpasync16(uS + idx * 16, Hb + (size_t)(idx >> 6) * 256 + (idx & 63) * 4);
        }
        CP_COMMIT();                                      // group: hist chunk 0
    }

    // ================= Phase 1: softmax (sc overlays Bsm) =================
    float* sc = (float*)Bsm;
    CP_WAIT(2);          // scores group complete
    __syncthreads();
    {
        const int ni = numInt[b];
        for (int k = w; k < 32; k += 8) {
            if (k >= ni) {
                for (int l = lane; l < LEN; l += 32) sc[k * 100 + l] = 0.01f;
            } else {
                float m = -3.4e38f;
                for (int l = lane; l < LEN; l += 32) m = fmaxf(m, sc[k * 100 + l]);
#pragma unroll
                for (int off = 16; off; off >>= 1)
                    m = fmaxf(m, __shfl_xor_sync(0xffffffffu, m, off));
                float ssum = 0.f;
                for (int l = lane; l < LEN; l += 32) {
                    float e = expf(sc[k * 100 + l] - m);
                    sc[k * 100 + l] = e;
                    ssum += e;
                }
#pragma unroll
                for (int off = 16; off; off >>= 1) ssum += __shfl_xor_sync(0xffffffffu, ssum, off);
                for (int l = lane; l < LEN; l += 32) sc[k * 100 + l] = sc[k * 100 + l] / ssum;
            }
        }
    }
    __syncthreads();

    // ================= Phase 2: attn splits -> Asm =================
    for (int idx = tid; idx < 2048; idx += 256) {
        const int k = idx >> 6;
        const int l2 = (idx & 63) * 2;
        const float v0 = (l2 < 100) ? sc[k * 100 + l2] : 0.f;
        const float v1 = (l2 + 1 < 100) ? sc[k * 100 + l2 + 1] : 0.f;
        uint32_t lo, hi;
        split_pack(v0, v1, lo, hi);
        const int h = l2 >> 6, ll = l2 & 63;
        const uint32_t off = SWZ((uint32_t)((h * 32 + k) * 128 + ll * 2));
        *(uint32_t*)(Asm + off)        = lo;
        *(uint32_t*)(Asm + 8192 + off) = hi;
    }

    // ================= Phase 3: interests mma, hist staged via cp.async =======
    const int pnl = w >> 1;
    const int sub = w & 1;
    float acc[2][2][2][4];
#pragma unroll
    for (int mt = 0; mt < 2; mt++)
#pragma unroll
        for (int ntt = 0; ntt < 2; ntt++)
#pragma unroll
            for (int n8 = 0; n8 < 2; n8++)
#pragma unroll
                for (int i = 0; i < 4; i++) acc[mt][ntt][n8][i] = 0.f;

    for (int ch = 0; ch < 4; ch++) {
        const int l0 = ch * 32;
        CP_WAIT(0);          // staged chunk ch (and any earlier groups) complete
        __syncthreads();     // also: all warps done reading Bsm from prev chunk

        // read staging -> split -> Bsm panels
#pragma unroll
        for (int t = 0; t < 8; t++) {
            const int idx = tid + t * 256;
            const int lr = idx >> 6, c4 = idx & 63;
            const int l = l0 + lr;
            float4 a = make_float4(0.f, 0.f, 0.f, 0.f);
            if (l < LEN) a = *(const float4*)&stage[(size_t)lr * 256 + c4 * 4];
            uint32_t lx, hx, ly, hy;
            split_pack(a.x, a.y, lx, hx);
            split_pack(a.z, a.w, ly, hy);
            const int d = c4 * 4;
            const int p = d >> 6, dcol = d & 63;
            const uint32_t off = p * 4096 + SWZ((uint32_t)(lr * 128 + dcol * 2));
            *(uint2*)(Bsm + off)         = make_uint2(lx, ly);
            *(uint2*)(Bsm + 16384 + off) = make_uint2(hx, hy);
        }
        __syncthreads();     // Bsm ready; staging reads complete

        // prefetch next chunk into staging (overlaps the mma below)
        if (ch + 1 < 4) {
            const int nl0 = (ch + 1) * 32;
#pragma unroll
            for (int t = 0; t < 8; t++) {
                const int idx = tid + t * 256;
                const int lr = idx >> 6;
                if (nl0 + lr < LEN)
                    cpasync16(uS + idx * 16, Hb + (size_t)(nl0 + lr) * 256 + (idx & 63) * 4);
            }
            CP_COMMIT();
        }

#pragma unroll
        for (int ks2 = 0; ks2 < 2; ks2++) {
            const int kk = l0 + ks2 * 16;
            const int half = kk >> 6, lloc = kk & 63;

            uint32_t a0[2][4], a1[2][4];
#pragma unroll
            for (int mt = 0; mt < 2; mt++) {
                const int row = mt * 16 + ((g & 1) << 3) + rw;
                const uint32_t ao = SWZ((uint32_t)((half * 32 + row) * 128 + (lloc + ((g >> 1) << 3)) * 2));
                ldsm4(a0[mt], uA + ao);
                ldsm4(a1[mt], uA + 8192 + ao);
            }

            const int trow = ks2 * 16 + (lane & 7) + ((lane >> 3) & 1) * 8;
            const int tcolb = ((lane >> 4) & 1) * 8;
#pragma unroll
            for (int ntt = 0; ntt < 2; ntt++) {
                const int ntg = sub * 2 + ntt;
                const uint32_t bo = pnl * 4096 + SWZ((uint32_t)(trow * 128 + (ntg * 16 + tcolb) * 2));
                uint32_t bl0[4], bl1[4];
                ldsm4t(bl0, uB + bo);
                ldsm4t(bl1, uB + 16384 + bo);
#pragma unroll
                for (int mt = 0; mt < 2; mt++) {
                    float* c0 = acc[mt][ntt][0];
                    float* c1 = acc[mt][ntt][1];
                    mma16816(c0, a0[mt], bl0[0], bl0[1]);
                    mma16816(c0, a0[mt], bl1[0], bl1[1]);
                    mma16816(c0, a1[mt], bl0[0], bl0[1]);
                    mma16816(c0, a1[mt], bl1[0], bl1[1]);
                    mma16816(c1, a0[mt], bl0[2], bl0[3]);
                    mma16816(c1, a0[mt], bl1[2], bl1[3]);
                    mma16816(c1, a1[mt], bl0[2], bl0[3]);
                    mma16816(c1, a1[mt], bl1[2], bl1[3]);
                }
            }
        }
    }
    __syncthreads();

    // ================= Phase 4: interests -> if32 + ism =================
#pragma unroll
    for (int mt = 0; mt < 2; mt++) {
#pragma unroll
        for (int ntt = 0; ntt < 2; ntt++) {
            const int ntg = sub * 2 + ntt;
#pragma unroll
            for (int n8 = 0; n8 < 2; n8++) {
                const int d = pnl * 64 + ntg * 16 + n8 * 8 + tig * 2;
#pragma unroll
                for (int hh = 0; hh < 2; hh++) {
                    const int kk = mt * 16 + gid + hh * 8;
                    const float vx = acc[mt][ntt][n8][hh * 2], vy = acc[mt][ntt][n8][hh * 2 + 1];
                    *(float2*)&if32[kk * 256 + d] = make_float2(vx, vy);
                    uint32_t lo, hi;
                    split_pack(vx, vy, lo, hi);
                    const int dloc = d & 63;
                    const uint32_t off = pnl * 4096 + SWZ((uint32_t)(kk * 128 + dloc * 2));
                    *(uint32_t*)(ism + off)         = lo;
                    *(uint32_t*)(ism + 16384 + off) = hi;
                }
            }
        }
    }
    __syncthreads();

    // ================= Phase 5: w-GEMM + rank, cp.async pipeline =================
    float* partial = (float*)(s + O_PART);
    float* wmaskT  = (float*)(s + O_WMT);

    u64 ireg2[16];
    {
        const u64* ibase = (const u64*)(if32 + lane * 256 + w * 32);
#pragma unroll
        for (int j = 0; j < 16; j++) ireg2[j] = ibase[j];
    }
    __syncthreads();

    const int cc = catCnt[b];
    int dynK = (int)ceilf(log2f(8.0f * (float)cc));
    dynK = dynK < 1 ? 1 : (dynK > 32 ? 32 : dynK);

    for (int n0 = 0; n0 < 64; n0 += 8) {
        const int buf = (n0 >> 3) & 1;
        if (n0 + 8 < 64) {
            const uint32_t uNxt = buf ? uC0 : uC1;
            const float* src = Cb + (size_t)(n0 + 8) * DIM;
            cpasync16(uNxt + tid * 16, src + tid * 4);
            cpasync16(uNxt + (tid + 256) * 16, src + (size_t)(tid + 256) * 4);
            CP_COMMIT();
            CP_WAIT(1);
        } else {
            CP_WAIT(0);
        }
        __syncthreads();

        const uint4* rbase4 = (const uint4*)(s + (buf ? O_CAND1 : O_CAND0));
        u64 p[8];
#pragma unroll
        for (int r = 0; r < 8; r++) p[r] = 0ull;
#pragma unroll
        for (int j4 = 0; j4 < 8; j4++) {
            const u64 iv0 = ireg2[j4 * 2], iv1 = ireg2[j4 * 2 + 1];
            const int coff = w * 8 + j4;
#pragma unroll
            for (int r = 0; r < 8; r++) {
                const uint4 v = rbase4[r * 64 + coff];
                p[r] = ffma2(iv0, packu(v.x, v.y), p[r]);
                p[r] = ffma2(iv1, packu(v.z, v.w), p[r]);
            }
        }
#pragma unroll
        for (int r = 0; r < 8; r++) {
            float2 t = unpack2(p[r]);
            partial[w * 256 + r * 32 + lane] = t.x + t.y;
        }
        __syncthreads();

        {
            const int k = lane, r = w;
            float ssum = 0.f;
#pragma unroll
            for (int ww = 0; ww < 8; ww++) ssum += partial[ww * 256 + r * 32 + k];
            wmaskT[(n0 + r) * 32 + k] = ssum;
        }
        __syncwarp();

        {
            const float wi = wmaskT[(n0 + w) * 32 + lane];
            int rank = 0;
#pragma unroll
            for (int j = 0; j < 32; j++) {
                const float wj = __shfl_sync(0xffffffffu, wi, j);
                rank += (wj > wi) || (wj == wi && j < lane);
            }
            wmaskT[(n0 + w) * 32 + lane] = (rank < dynK) ? wi : 0.f;
        }
        __syncthreads();
    }

    // ================= Phase 6: wmask fp16 splits =================
    char* wmsm = s + O_WMS;
    const uint32_t uW = sb + O_WMS;
    for (int idx = tid; idx < 2048; idx += 256) {
        const int r = idx >> 5, c = idx & 31;
        const float v = wmaskT[r * 32 + c];
        const __half m1 = __float2half_rn(v);
        const __half m2 = __float2half_rn(v - __half2float(m1));
        const uint32_t off = SWZ((uint32_t)(r * 128 + c * 2));
        *(__half*)(wmsm + off)        = m1;
        *(__half*)(wmsm + 8192 + off) = m2;
    }
    __syncthreads();

    // ================= Phase 7: user mma (3-pass) =================
    const int mt = w & 3;
    const int phh = w >> 2;

    float* Ob = out + (size_t)b * NCAND * DIM;
#pragma unroll
    for (int pp = 0; pp < 2; pp++) {
        const int pn = phh * 2 + pp;

        float ua[4][2][4];
#pragma unroll
        for (int ntt = 0; ntt < 4; ntt++)
#pragma unroll
            for (int n8 = 0; n8 < 2; n8++)
#pragma unroll
                for (int i = 0; i < 4; i++) ua[ntt][n8][i] = 0.f;

#pragma unroll
        for (int ks = 0; ks < 2; ks++) {
            const int arow = mt * 16 + ((g & 1) << 3) + rw;
            const int acol = ks * 16 + ((g >> 1) << 3);
            const uint32_t ao = SWZ((uint32_t)(arow * 128 + acol * 2));
            uint32_t am1[4], am2[4];
            ldsm4(am1, uW + ao);
            ldsm4(am2, uW + 8192 + ao);

            const int trow = ks * 16 + (lane & 7) + ((lane >> 3) & 1) * 8;
            const int tcolb = ((lane >> 4) & 1) * 8;
#pragma unroll
            for (int ntt = 0; ntt < 4; ntt++) {
                const uint32_t bo = pn * 4096 + SWZ((uint32_t)(trow * 128 + (ntt * 16 + tcolb) * 2));
                uint32_t bi1[4], bi2[4];
                ldsm4t(bi1, uI + bo);
                ldsm4t(bi2, uI + 16384 + bo);
#pragma unroll
                for (int n8 = 0; n8 < 2; n8++) {
                    float* c = ua[ntt][n8];
                    mma16816(c, am1, bi1[n8 * 2], bi1[n8 * 2 + 1]);
                    mma16816(c, am1, bi2[n8 * 2], bi2[n8 * 2 + 1]);
                    mma16816(c, am2, bi1[n8 * 2], bi1[n8 * 2 + 1]);
                }
            }
        }

#pragma unroll
        for (int ntt = 0; ntt < 4; ntt++) {
#pragma unroll
            for (int n8 = 0; n8 < 2; n8++) {
                const int d = pn * 64 + ntt * 16 + n8 * 8 + tig * 2;
                const int r0 = mt * 16 + gid;
                *(float2*)&Ob[(size_t)r0 * 256 + d]       = make_float2(ua[ntt][n8][0], ua[ntt][n8][1]);
                *(float2*)&Ob[(size_t)(r0 + 8) * 256 + d] = make_float2(ua[ntt][n8][2], ua[ntt][n8][3]);
            }
        }
    }
}

// ---------------------------------------------------------------------------
extern "C" void kernel_launch(void* const* d_in, const int* in_sizes, int n_in,
                              void* d_out, int out_size) {
    (void)in_sizes; (void)n_in; (void)out_size;
    const float* hist  = (const float*)d_in[0];
    const float* cand  = (const float*)d_in[2];
    const int*   numI  = (const int*)d_in[3];
    const int*   catC  = (const int*)d_in[4];
    const float* W     = (const float*)d_in[5];
    const float* codes = (const float*)d_in[6];
    float* out = (float*)d_out;

    static bool attr_set = false;
    if (!attr_set) {
        cudaFuncSetAttribute(k1_mma, cudaFuncAttributeMaxDynamicSharedMemorySize, K1_SMEM);
        cudaFuncSetAttribute(k24, cudaFuncAttributeMaxDynamicSharedMemorySize, K24_SMEM);
        attr_set = true;
    }

    kw_split<<<256, 256>>>(W);
    k1_mma<<<dim3(2, 400), 256, K1_SMEM>>>(hist);
    k2a_kernel<<<400, 128>>>(codes);
    k24<<<BSZ, 256, K24_SMEM>>>(hist, numI, cand, catC, out);
}